// round 7
// baseline (speedup 1.0000x reference)
#include <cuda_runtime.h>
#include <cuda_bf16.h>

// Problem dims
#define BB    32
#define SS    512
#define WIN   5
#define EMB   300
#define HH    300
#define K1    1500        // EMB*WIN
#define NOUT  128
#define MROWS (BB*SS)     // 16384

// ------------------------------------------------------------------
// Scratch (static device globals)
// ------------------------------------------------------------------
__device__ float g_XE[(size_t)MROWS * K1];   // relu(embedded)
__device__ float g_A [(size_t)MROWS * HH];   // pre-activation (A1 then A2)
__device__ float g_H1[(size_t)MROWS * HH];   // layer1 hidden states [s*32+b][300]
__device__ float g_H2[(size_t)MROWS * HH];   // layer2 hidden states

// ------------------------------------------------------------------
// helpers
// ------------------------------------------------------------------
__device__ __forceinline__ void ffma2(unsigned long long &d,
                                      unsigned long long a,
                                      unsigned long long b) {
    asm("fma.rn.f32x2 %0, %1, %2, %0;" : "+l"(d) : "l"(a), "l"(b));
}
__device__ __forceinline__ unsigned long long pack2(float lo, float hi) {
    unsigned long long r;
    asm("mov.b64 %0, {%1, %2};" : "=l"(r) : "f"(lo), "f"(hi));
    return r;
}
__device__ __forceinline__ void unpack2(unsigned long long v, float &lo, float &hi) {
    asm("mov.b64 {%0, %1}, %2;" : "=f"(lo), "=f"(hi) : "l"(v));
}
__device__ __forceinline__ unsigned smem_u32(const void *p) {
    unsigned a;
    asm("{ .reg .u64 t; cvta.to.shared.u64 t, %1; cvt.u32.u64 %0, t; }"
        : "=r"(a) : "l"(p));
    return a;
}
// tanh via MUFU: 1 - 2/(exp2(2x*log2e)+1). abs err ~1e-7, no division.
__device__ __forceinline__ float tanh_fast(float x) {
    float e;
    asm("ex2.approx.f32 %0, %1;" : "=f"(e) : "f"(x * 2.88539008177792681f));
    float r;
    asm("rcp.approx.f32 %0, %1;" : "=f"(r) : "f"(e + 1.0f));
    return fmaf(-2.0f, r, 1.0f);
}

// ------------------------------------------------------------------
// Kernel 1: embedding gather + relu
// ------------------------------------------------------------------
__global__ void embed_kernel(const int *__restrict__ x,
                             const float *__restrict__ emb) {
    int m = blockIdx.x;            // m = s*32 + b
    int s = m >> 5, b = m & 31;
    __shared__ int idx[WIN];
    if (threadIdx.x < WIN) idx[threadIdx.x] = x[(b * SS + s) * WIN + threadIdx.x];
    __syncthreads();
    float4 *out4 = reinterpret_cast<float4 *>(g_XE + (size_t)m * K1);
    for (int i = threadIdx.x; i < K1 / 4; i += blockDim.x) {
        int e4 = i * 4;
        int w = e4 / EMB;
        int e = e4 - w * EMB;
        float4 v = *reinterpret_cast<const float4 *>(emb + (size_t)idx[w] * EMB + e);
        v.x = fmaxf(v.x, 0.f); v.y = fmaxf(v.y, 0.f);
        v.z = fmaxf(v.z, 0.f); v.w = fmaxf(v.w, 0.f);
        out4[i] = v;
    }
}

// ------------------------------------------------------------------
// GEMM (double-buffered): C[m][n] = sum_k A[m][k]*Bw[n][k] + b1[n] (+ b2[n])
// BM=128, BN=64, BK=16, 256 threads, 4x8 thread tile via f32x2.
// One __syncthreads per k-tile; LDG of tile kt+1 overlaps compute of kt.
// ------------------------------------------------------------------
template <bool PERM>
__global__ __launch_bounds__(256)
void gemm_nt(const float *__restrict__ A, const float *__restrict__ Bw,
             const float *__restrict__ b1, const float *__restrict__ b2,
             float *__restrict__ C, int M, int N, int K, int ldc) {
    __shared__ __align__(16) float As[2][16][132];
    __shared__ __align__(16) float Bs[2][16][68];

    const int tid = threadIdx.x;
    const int m0 = blockIdx.y * 128;
    const int n0 = blockIdx.x * 64;
    const int tx = tid & 7;
    const int ty = tid >> 3;
    const int a_r = tid >> 2;
    const int a_k = (tid & 3) * 4;

    unsigned long long acc[4][4];
#pragma unroll
    for (int i = 0; i < 4; i++)
#pragma unroll
        for (int j = 0; j < 4; j++) acc[i][j] = 0ULL;

    const int KT = (K + 15) >> 4;

    // prologue: load + store tile 0
    {
        float4 av0 = make_float4(0.f, 0.f, 0.f, 0.f), av1 = av0, bv = av0;
        int kk = a_k;
        if (kk < K) {
            av0 = *reinterpret_cast<const float4 *>(A + (size_t)(m0 + a_r) * K + kk);
            av1 = *reinterpret_cast<const float4 *>(A + (size_t)(m0 + a_r + 64) * K + kk);
            if (n0 + a_r < N)
                bv = *reinterpret_cast<const float4 *>(Bw + (size_t)(n0 + a_r) * K + kk);
        }
        As[0][a_k + 0][a_r] = av0.x; As[0][a_k + 1][a_r] = av0.y;
        As[0][a_k + 2][a_r] = av0.z; As[0][a_k + 3][a_r] = av0.w;
        As[0][a_k + 0][a_r + 64] = av1.x; As[0][a_k + 1][a_r + 64] = av1.y;
        As[0][a_k + 2][a_r + 64] = av1.z; As[0][a_k + 3][a_r + 64] = av1.w;
        Bs[0][a_k + 0][a_r] = bv.x; Bs[0][a_k + 1][a_r] = bv.y;
        Bs[0][a_k + 2][a_r] = bv.z; Bs[0][a_k + 3][a_r] = bv.w;
    }
    __syncthreads();

    for (int kt = 0; kt < KT; kt++) {
        const int cb = kt & 1;
        float4 av0 = make_float4(0.f, 0.f, 0.f, 0.f), av1 = av0, bv = av0;
        const bool more = (kt + 1 < KT);
        if (more) {
            int kk = (kt + 1) * 16 + a_k;
            if (kk < K) {
                av0 = *reinterpret_cast<const float4 *>(A + (size_t)(m0 + a_r) * K + kk);
                av1 = *reinterpret_cast<const float4 *>(A + (size_t)(m0 + a_r + 64) * K + kk);
                if (n0 + a_r < N)
                    bv = *reinterpret_cast<const float4 *>(Bw + (size_t)(n0 + a_r) * K + kk);
            }
        }

#pragma unroll
        for (int k = 0; k < 16; k++) {
            float4 a4 = *reinterpret_cast<const float4 *>(&As[cb][k][ty * 4]);
            const ulonglong2 *bp =
                reinterpret_cast<const ulonglong2 *>(&Bs[cb][k][tx * 8]);
            ulonglong2 bA = bp[0], bB = bp[1];
            unsigned long long a0 = pack2(a4.x, a4.x);
            unsigned long long a1 = pack2(a4.y, a4.y);
            unsigned long long a2 = pack2(a4.z, a4.z);
            unsigned long long a3 = pack2(a4.w, a4.w);
            ffma2(acc[0][0], a0, bA.x); ffma2(acc[0][1], a0, bA.y);
            ffma2(acc[0][2], a0, bB.x); ffma2(acc[0][3], a0, bB.y);
            ffma2(acc[1][0], a1, bA.x); ffma2(acc[1][1], a1, bA.y);
            ffma2(acc[1][2], a1, bB.x); ffma2(acc[1][3], a1, bB.y);
            ffma2(acc[2][0], a2, bA.x); ffma2(acc[2][1], a2, bA.y);
            ffma2(acc[2][2], a2, bB.x); ffma2(acc[2][3], a2, bB.y);
            ffma2(acc[3][0], a3, bA.x); ffma2(acc[3][1], a3, bA.y);
            ffma2(acc[3][2], a3, bB.x); ffma2(acc[3][3], a3, bB.y);
        }

        if (more) {
            const int nb = cb ^ 1;
            As[nb][a_k + 0][a_r] = av0.x; As[nb][a_k + 1][a_r] = av0.y;
            As[nb][a_k + 2][a_r] = av0.z; As[nb][a_k + 3][a_r] = av0.w;
            As[nb][a_k + 0][a_r + 64] = av1.x; As[nb][a_k + 1][a_r + 64] = av1.y;
            As[nb][a_k + 2][a_r + 64] = av1.z; As[nb][a_k + 3][a_r + 64] = av1.w;
            Bs[nb][a_k + 0][a_r] = bv.x; Bs[nb][a_k + 1][a_r] = bv.y;
            Bs[nb][a_k + 2][a_r] = bv.z; Bs[nb][a_k + 3][a_r] = bv.w;
        }
        __syncthreads();
    }

    float bias[8];
#pragma unroll
    for (int jj = 0; jj < 8; jj++) {
        int n = n0 + tx * 8 + jj;
        bias[jj] = (n < N) ? (b1[n] + (b2 ? b2[n] : 0.f)) : 0.f;
    }
#pragma unroll
    for (int i = 0; i < 4; i++) {
        int m = m0 + ty * 4 + i;
        int row = PERM ? ((m & 31) * SS + (m >> 5)) : m;
        float *cp = C + (size_t)row * ldc;
#pragma unroll
        for (int j = 0; j < 4; j++) {
            int n = n0 + tx * 8 + 2 * j;
            float lo, hi;
            unpack2(acc[i][j], lo, hi);
            if (n < N)     cp[n]     = lo + bias[2 * j];
            if (n + 1 < N) cp[n + 1] = hi + bias[2 * j + 1];
        }
    }
}

// ------------------------------------------------------------------
// Recurrence, K-split, flag-based exchange (NO mbarriers, NO cluster
// barriers in the loop).
// One batch element per 4-CTA cluster. CTA r holds W[:, 75r:+75] in regs.
// Per step:
//   1) thread j (<300) computes p_j = dot(W[j,slice], hloc(t-1)); writes it
//      into the owner CTA's inbox[pb][rank][j%75] — locally if owner==rank,
//      else ONE weak st.shared::cluster (fire-and-forget).
//   2) __syncthreads; 3 flagger threads: fence.acq_rel.cluster (cumulative:
//      covers all threads' remote stores via the bar) + st.release of t+1
//      into each peer's flag[pb][rank].
//   3) owner threads (tid<75) spin on the 3 LOCAL flags (ld.acquire,
//      29-cyc polls) until >= t+1, then sum 4 inbox slabs + A, tanh,
//      publish h chunk locally; __syncthreads.
// Inbox/flags parity-double-buffered; dependence chain guarantees a t+2
// write can never overwrite unread t data.
// ------------------------------------------------------------------
__global__ void __cluster_dims__(4, 1, 1) __launch_bounds__(320)
rec_kernel(const float *__restrict__ W, const float *__restrict__ A,
           float *__restrict__ Hout) {
    __shared__ __align__(16) float hloc[2][80];      // my h chunk (75 + pad)
    __shared__ __align__(16) float inbox[2][4][80];  // [pb][srcCTA][slot]
    __shared__ unsigned flags[2][4];                 // [pb][srcCTA]

    const int tid  = threadIdx.x;
    const int rank = blockIdx.x & 3;
    const int b    = blockIdx.x >> 2;
    const bool active = tid < 300;
    const int dst  = active ? (tid / 75) : 0;    // owner CTA of row tid
    const int slot = active ? (tid % 75) : 0;

    // W column-slice: thread j holds W[j, 75*rank .. 75*rank+74], packed f32x2.
    unsigned long long w2[38];
    if (active) {
        const float *wp = W + (size_t)tid * HH + rank * 75;
#pragma unroll
        for (int i = 0; i < 37; i++) w2[i] = pack2(wp[2 * i], wp[2 * i + 1]);
        w2[37] = pack2(wp[74], 0.f);
    }
    for (int i = tid; i < 2 * 80; i += blockDim.x) (&hloc[0][0])[i] = 0.f;
    if (tid < 8) flags[tid >> 2][tid & 3] = 0u;
    __syncthreads();
    asm volatile("barrier.cluster.arrive.aligned;" ::: "memory");
    asm volatile("barrier.cluster.wait.aligned;" ::: "memory");

    // loop-invariant remote inbox addresses (per parity)
    unsigned in_rem[2];
    const bool remote = active && (dst != rank);
    if (remote) {
#pragma unroll
        for (int p = 0; p < 2; p++) {
            unsigned lp = smem_u32(&inbox[p][rank][slot]);
            asm("mapa.shared::cluster.u32 %0, %1, %2;"
                : "=r"(in_rem[p]) : "r"(lp), "r"(dst));
        }
    }
    // flagger threads: 300,301,302 -> peers
    unsigned fl_rem[2];
    const bool flagger = (tid >= 300 && tid < 303);
    if (flagger) {
        int d = (rank + 1 + (tid - 300)) & 3;
#pragma unroll
        for (int p = 0; p < 2; p++) {
            unsigned lf = smem_u32(&flags[p][rank]);
            asm("mapa.shared::cluster.u32 %0, %1, %2;"
                : "=r"(fl_rem[p]) : "r"(lf), "r"(d));
        }
    }
    const int s1 = (rank + 1) & 3, s2 = (rank + 2) & 3, s3 = (rank + 3) & 3;
    unsigned fl_loc1[2], fl_loc2[2], fl_loc3[2];
#pragma unroll
    for (int p = 0; p < 2; p++) {
        fl_loc1[p] = smem_u32(&flags[p][s1]);
        fl_loc2[p] = smem_u32(&flags[p][s2]);
        fl_loc3[p] = smem_u32(&flags[p][s3]);
    }

    const float *arow = A + (size_t)b * HH + rank * 75;
    float *hrow = Hout + (size_t)b * HH + rank * 75;

    float a_cur = (tid < 75) ? arow[tid] : 0.f;

    for (int t = 0; t < SS; t++) {
        const int pb = t & 1;
        float a_nxt = 0.f;
        if (tid < 75 && t + 1 < SS)
            a_nxt = arow[(size_t)(t + 1) * BB * HH + tid];

        if (active) {
            // p_j = dot(W[j, slice], h_slice(t-1));  h(t-1) in hloc[pb^1]
            const ulonglong2 *hp2 =
                reinterpret_cast<const ulonglong2 *>(&hloc[pb ^ 1][0]);
            unsigned long long c0 = 0ULL, c1 = 0ULL, c2 = 0ULL, c3 = 0ULL;
#pragma unroll
            for (int k = 0; k < 19; k++) {
                ulonglong2 hv = hp2[k];
                if (k & 1) { ffma2(c2, w2[2*k], hv.x); ffma2(c3, w2[2*k+1], hv.y); }
                else       { ffma2(c0, w2[2*k], hv.x); ffma2(c1, w2[2*k+1], hv.y); }
            }
            float l0, h0, l1, h1, l2, h2, l3, h3;
            unpack2(c0, l0, h0); unpack2(c1, l1, h1);
            unpack2(c2, l2, h2); unpack2(c3, l3, h3);
            float p = ((l0 + h0) + (l1 + h1)) + ((l2 + h2) + (l3 + h3));
            if (remote) {
                asm volatile("st.shared::cluster.f32 [%0], %1;"
                             :: "r"(in_rem[pb]), "f"(p) : "memory");
            } else {
                inbox[pb][rank][slot] = p;
            }
        }
        __syncthreads();   // all local+remote partial stores issued; local visible

        if (flagger) {
            asm volatile("fence.acq_rel.cluster;" ::: "memory");
            asm volatile("st.release.cluster.shared::cluster.u32 [%0], %1;"
                         :: "r"(fl_rem[pb]), "r"((unsigned)(t + 1)) : "memory");
        }

        if (tid < 75) {
            const unsigned want = (unsigned)(t + 1);
            unsigned f;
            do { asm volatile("ld.acquire.cluster.shared::cta.u32 %0, [%1];"
                              : "=r"(f) : "r"(fl_loc1[pb]) : "memory"); } while (f < want);
            do { asm volatile("ld.acquire.cluster.shared::cta.u32 %0, [%1];"
                              : "=r"(f) : "r"(fl_loc2[pb]) : "memory"); } while (f < want);
            do { asm volatile("ld.acquire.cluster.shared::cta.u32 %0, [%1];"
                              : "=r"(f) : "r"(fl_loc3[pb]) : "memory"); } while (f < want);

            float s = a_cur
                    + inbox[pb][0][tid] + inbox[pb][1][tid]
                    + inbox[pb][2][tid] + inbox[pb][3][tid];
            float hv = tanh_fast(s);
            hrow[(size_t)t * BB * HH + tid] = hv;
            hloc[pb][tid] = hv;
        }
        a_cur = a_nxt;
        __syncthreads();   // publish hloc[pb] for step t+1
    }

    asm volatile("barrier.cluster.arrive.aligned;" ::: "memory");
    asm volatile("barrier.cluster.wait.aligned;" ::: "memory");
}

// ------------------------------------------------------------------
// Launch sequence
// ------------------------------------------------------------------
extern "C" void kernel_launch(void *const *d_in, const int *in_sizes, int n_in,
                              void *d_out, int out_size) {
    const int   *x     = (const int *)d_in[0];
    const float *emb   = (const float *)d_in[1];
    const float *W_ih1 = (const float *)d_in[2];
    const float *W_hh1 = (const float *)d_in[3];
    const float *b_ih1 = (const float *)d_in[4];
    const float *b_hh1 = (const float *)d_in[5];
    const float *W_ih2 = (const float *)d_in[6];
    const float *W_hh2 = (const float *)d_in[7];
    const float *b_ih2 = (const float *)d_in[8];
    const float *b_hh2 = (const float *)d_in[9];
    const float *fc1_w = (const float *)d_in[10];
    const float *fc1_b = (const float *)d_in[11];
    const float *fc2_w = (const float *)d_in[12];
    const float *fc2_b = (const float *)d_in[13];
    float *out = (float *)d_out;

    float *xe, *a, *h1, *h2;
    cudaGetSymbolAddress((void **)&xe, g_XE);
    cudaGetSymbolAddress((void **)&a,  g_A);
    cudaGetSymbolAddress((void **)&h1, g_H1);
    cudaGetSymbolAddress((void **)&h2, g_H2);

    // 1) embed + relu
    embed_kernel<<<MROWS, 128>>>(x, emb);

    // 2) A1 = XE @ W_ih1^T + (b_ih1 + b_hh1)
    {
        dim3 grid((HH + 63) / 64, MROWS / 128);
        gemm_nt<false><<<grid, 256>>>(xe, W_ih1, b_ih1, b_hh1, a,
                                      MROWS, HH, K1, HH);
    }
    // 3) layer-1 recurrence -> H1
    rec_kernel<<<128, 320>>>(W_hh1, a, h1);

    // 4) A2 = H1 @ W_ih2^T + (b_ih2 + b_hh2)
    {
        dim3 grid((HH + 63) / 64, MROWS / 128);
        gemm_nt<false><<<grid, 256>>>(h1, W_ih2, b_ih2, b_hh2, a,
                                      MROWS, HH, HH, HH);
    }
    // 5) layer-2 recurrence -> H2
    rec_kernel<<<128, 320>>>(W_hh2, a, h2);

    // 6) projections (permuted store: m = s*32+b -> row b*512+s)
    {
        dim3 grid((NOUT + 63) / 64, MROWS / 128);
        gemm_nt<true><<<grid, 256>>>(h1, fc1_w, fc1_b, nullptr, out,
                                     MROWS, NOUT, HH, NOUT);
        gemm_nt<true><<<grid, 256>>>(h2, fc2_w, fc2_b, nullptr,
                                     out + (size_t)MROWS * NOUT,
                                     MROWS, NOUT, HH, NOUT);
    }
}

// round 8
// speedup vs baseline: 1.3805x; 1.3805x over previous
#include <cuda_runtime.h>
#include <cuda_bf16.h>

// Problem dims
#define BB    32
#define SS    512
#define WIN   5
#define EMB   300
#define HH    300
#define K1    1500        // EMB*WIN
#define NOUT  128
#define MROWS (BB*SS)     // 16384

// ------------------------------------------------------------------
// Scratch (static device globals)
// ------------------------------------------------------------------
__device__ float g_XE[(size_t)MROWS * K1];   // relu(embedded)
__device__ float g_A [(size_t)MROWS * HH];   // pre-activation (A1 then A2)
__device__ float g_H1[(size_t)MROWS * HH];   // layer1 hidden states [s*32+b][300]
__device__ float g_H2[(size_t)MROWS * HH];   // layer2 hidden states

// ------------------------------------------------------------------
// helpers
// ------------------------------------------------------------------
__device__ __forceinline__ void ffma2(unsigned long long &d,
                                      unsigned long long a,
                                      unsigned long long b) {
    asm("fma.rn.f32x2 %0, %1, %2, %0;" : "+l"(d) : "l"(a), "l"(b));
}
__device__ __forceinline__ unsigned long long pack2(float lo, float hi) {
    unsigned long long r;
    asm("mov.b64 %0, {%1, %2};" : "=l"(r) : "f"(lo), "f"(hi));
    return r;
}
__device__ __forceinline__ void unpack2(unsigned long long v, float &lo, float &hi) {
    asm("mov.b64 {%0, %1}, %2;" : "=f"(lo), "=f"(hi) : "l"(v));
}
__device__ __forceinline__ unsigned smem_u32(const void *p) {
    unsigned a;
    asm("{ .reg .u64 t; cvta.to.shared.u64 t, %1; cvt.u32.u64 %0, t; }"
        : "=r"(a) : "l"(p));
    return a;
}
// tanh via MUFU: 1 - 2/(exp2(2x*log2e)+1). abs err ~1e-7, no division.
__device__ __forceinline__ float tanh_fast(float x) {
    float e;
    asm("ex2.approx.f32 %0, %1;" : "=f"(e) : "f"(x * 2.88539008177792681f));
    float r;
    asm("rcp.approx.f32 %0, %1;" : "=f"(r) : "f"(e + 1.0f));
    return fmaf(-2.0f, r, 1.0f);
}

// ------------------------------------------------------------------
// Kernel 1: embedding gather + relu
// ------------------------------------------------------------------
__global__ void embed_kernel(const int *__restrict__ x,
                             const float *__restrict__ emb) {
    int m = blockIdx.x;            // m = s*32 + b
    int s = m >> 5, b = m & 31;
    __shared__ int idx[WIN];
    if (threadIdx.x < WIN) idx[threadIdx.x] = x[(b * SS + s) * WIN + threadIdx.x];
    __syncthreads();
    float4 *out4 = reinterpret_cast<float4 *>(g_XE + (size_t)m * K1);
    for (int i = threadIdx.x; i < K1 / 4; i += blockDim.x) {
        int e4 = i * 4;
        int w = e4 / EMB;
        int e = e4 - w * EMB;
        float4 v = *reinterpret_cast<const float4 *>(emb + (size_t)idx[w] * EMB + e);
        v.x = fmaxf(v.x, 0.f); v.y = fmaxf(v.y, 0.f);
        v.z = fmaxf(v.z, 0.f); v.w = fmaxf(v.w, 0.f);
        out4[i] = v;
    }
}

// ------------------------------------------------------------------
// GEMM: C[m][n] = sum_k A[m][k]*Bw[n][k] + b1[n] (+ b2[n])
// BM=128, BN=128, BK=16, 256 threads, 8x8 thread tile via f32x2.
// Double-buffered SMEM; 4 LDS.128 per 32 ffma2 -> fma-bound, not L1-bound.
// ------------------------------------------------------------------
template <bool PERM>
__global__ __launch_bounds__(256)
void gemm_nt(const float *__restrict__ A, const float *__restrict__ Bw,
             const float *__restrict__ b1, const float *__restrict__ b2,
             float *__restrict__ C, int M, int N, int K, int ldc) {
    __shared__ __align__(16) float As[2][16][132];
    __shared__ __align__(16) float Bs[2][16][132];

    const int tid = threadIdx.x;
    const int m0 = blockIdx.y * 128;
    const int n0 = blockIdx.x * 128;
    const int tx = tid & 15;        // 16 col groups * 8 cols
    const int ty = tid >> 4;        // 16 row groups * 8 rows
    const int lr = tid >> 1;        // loader row 0..127
    const int lk = (tid & 1) * 8;   // loader k base {0, 8}

    unsigned long long acc[8][4];
#pragma unroll
    for (int i = 0; i < 8; i++)
#pragma unroll
        for (int j = 0; j < 4; j++) acc[i][j] = 0ULL;

    const int KT = (K + 15) >> 4;

    // prologue: tile 0 -> buf 0
    {
        float4 a0 = make_float4(0.f,0.f,0.f,0.f), a1 = a0, v0 = a0, v1 = a0;
        int kk = lk;
        const float *ap = A + (size_t)(m0 + lr) * K;
        if (kk     < K) a0 = *reinterpret_cast<const float4 *>(ap + kk);
        if (kk + 4 < K) a1 = *reinterpret_cast<const float4 *>(ap + kk + 4);
        if (n0 + lr < N) {
            const float *bp = Bw + (size_t)(n0 + lr) * K;
            if (kk     < K) v0 = *reinterpret_cast<const float4 *>(bp + kk);
            if (kk + 4 < K) v1 = *reinterpret_cast<const float4 *>(bp + kk + 4);
        }
        As[0][lk+0][lr]=a0.x; As[0][lk+1][lr]=a0.y; As[0][lk+2][lr]=a0.z; As[0][lk+3][lr]=a0.w;
        As[0][lk+4][lr]=a1.x; As[0][lk+5][lr]=a1.y; As[0][lk+6][lr]=a1.z; As[0][lk+7][lr]=a1.w;
        Bs[0][lk+0][lr]=v0.x; Bs[0][lk+1][lr]=v0.y; Bs[0][lk+2][lr]=v0.z; Bs[0][lk+3][lr]=v0.w;
        Bs[0][lk+4][lr]=v1.x; Bs[0][lk+5][lr]=v1.y; Bs[0][lk+6][lr]=v1.z; Bs[0][lk+7][lr]=v1.w;
    }
    __syncthreads();

    for (int kt = 0; kt < KT; kt++) {
        const int cb = kt & 1;
        float4 a0 = make_float4(0.f,0.f,0.f,0.f), a1 = a0, v0 = a0, v1 = a0;
        const bool more = (kt + 1 < KT);
        if (more) {
            int kk = (kt + 1) * 16 + lk;
            const float *ap = A + (size_t)(m0 + lr) * K;
            if (kk     < K) a0 = *reinterpret_cast<const float4 *>(ap + kk);
            if (kk + 4 < K) a1 = *reinterpret_cast<const float4 *>(ap + kk + 4);
            if (n0 + lr < N) {
                const float *bp = Bw + (size_t)(n0 + lr) * K;
                if (kk     < K) v0 = *reinterpret_cast<const float4 *>(bp + kk);
                if (kk + 4 < K) v1 = *reinterpret_cast<const float4 *>(bp + kk + 4);
            }
        }

#pragma unroll
        for (int k = 0; k < 16; k++) {
            float4 aA = *reinterpret_cast<const float4 *>(&As[cb][k][ty * 8]);
            float4 aB = *reinterpret_cast<const float4 *>(&As[cb][k][ty * 8 + 4]);
            ulonglong2 bA = *reinterpret_cast<const ulonglong2 *>(&Bs[cb][k][tx * 8]);
            ulonglong2 bB = *reinterpret_cast<const ulonglong2 *>(&Bs[cb][k][tx * 8 + 4]);
            unsigned long long p0 = pack2(aA.x, aA.x), p1 = pack2(aA.y, aA.y);
            unsigned long long p2 = pack2(aA.z, aA.z), p3 = pack2(aA.w, aA.w);
            unsigned long long p4 = pack2(aB.x, aB.x), p5 = pack2(aB.y, aB.y);
            unsigned long long p6 = pack2(aB.z, aB.z), p7 = pack2(aB.w, aB.w);
            ffma2(acc[0][0], p0, bA.x); ffma2(acc[0][1], p0, bA.y);
            ffma2(acc[0][2], p0, bB.x); ffma2(acc[0][3], p0, bB.y);
            ffma2(acc[1][0], p1, bA.x); ffma2(acc[1][1], p1, bA.y);
            ffma2(acc[1][2], p1, bB.x); ffma2(acc[1][3], p1, bB.y);
            ffma2(acc[2][0], p2, bA.x); ffma2(acc[2][1], p2, bA.y);
            ffma2(acc[2][2], p2, bB.x); ffma2(acc[2][3], p2, bB.y);
            ffma2(acc[3][0], p3, bA.x); ffma2(acc[3][1], p3, bA.y);
            ffma2(acc[3][2], p3, bB.x); ffma2(acc[3][3], p3, bB.y);
            ffma2(acc[4][0], p4, bA.x); ffma2(acc[4][1], p4, bA.y);
            ffma2(acc[4][2], p4, bB.x); ffma2(acc[4][3], p4, bB.y);
            ffma2(acc[5][0], p5, bA.x); ffma2(acc[5][1], p5, bA.y);
            ffma2(acc[5][2], p5, bB.x); ffma2(acc[5][3], p5, bB.y);
            ffma2(acc[6][0], p6, bA.x); ffma2(acc[6][1], p6, bA.y);
            ffma2(acc[6][2], p6, bB.x); ffma2(acc[6][3], p6, bB.y);
            ffma2(acc[7][0], p7, bA.x); ffma2(acc[7][1], p7, bA.y);
            ffma2(acc[7][2], p7, bB.x); ffma2(acc[7][3], p7, bB.y);
        }

        if (more) {
            const int nb = cb ^ 1;
            As[nb][lk+0][lr]=a0.x; As[nb][lk+1][lr]=a0.y; As[nb][lk+2][lr]=a0.z; As[nb][lk+3][lr]=a0.w;
            As[nb][lk+4][lr]=a1.x; As[nb][lk+5][lr]=a1.y; As[nb][lk+6][lr]=a1.z; As[nb][lk+7][lr]=a1.w;
            Bs[nb][lk+0][lr]=v0.x; Bs[nb][lk+1][lr]=v0.y; Bs[nb][lk+2][lr]=v0.z; Bs[nb][lk+3][lr]=v0.w;
            Bs[nb][lk+4][lr]=v1.x; Bs[nb][lk+5][lr]=v1.y; Bs[nb][lk+6][lr]=v1.z; Bs[nb][lk+7][lr]=v1.w;
        }
        __syncthreads();
    }

    // epilogue
    float bias[8];
#pragma unroll
    for (int jj = 0; jj < 8; jj++) {
        int n = n0 + tx * 8 + jj;
        bias[jj] = (n < N) ? (b1[n] + (b2 ? b2[n] : 0.f)) : 0.f;
    }
    const int nbase = n0 + tx * 8;
    const bool full = (nbase + 8 <= N);
#pragma unroll
    for (int i = 0; i < 8; i++) {
        int m = m0 + ty * 8 + i;
        int row = PERM ? ((m & 31) * SS + (m >> 5)) : m;
        float *cp = C + (size_t)row * ldc;
        float v[8];
#pragma unroll
        for (int j = 0; j < 4; j++) {
            float lo, hi;
            unpack2(acc[i][j], lo, hi);
            v[2*j]   = lo + bias[2*j];
            v[2*j+1] = hi + bias[2*j+1];
        }
        if (full) {
            *reinterpret_cast<float4 *>(cp + nbase)     = make_float4(v[0], v[1], v[2], v[3]);
            *reinterpret_cast<float4 *>(cp + nbase + 4) = make_float4(v[4], v[5], v[6], v[7]);
        } else {
#pragma unroll
            for (int j = 0; j < 8; j++)
                if (nbase + j < N) cp[nbase + j] = v[j];
        }
    }
}

// ------------------------------------------------------------------
// Recurrence, K-split, TAGGED-DATA exchange.
// One batch element per 4-CTA cluster. CTA r holds W[:, 75r:+75] in regs
// (thread j: row j, its k-slice). Per step:
//   1) thread j computes p_j = dot(W[j,slice], hloc(t-1)) and sends ONE
//      st.relaxed.cluster.b64 {f32 p_j, u32 t} to the owner CTA's inbox
//      slot (parity-buffered). NO fence, NO mbarrier, NO flag — the tag
//      rides in the same 8-byte atom as the value.
//   2) owner threads (tid<75) spin on LOCAL ld.relaxed.b64 of their 4 inbox
//      slots until tag==t, sum + A, tanh, publish h chunk; __syncthreads.
// Overwrite safety: slot for step t is rewritten at t+2; producer reaches
// t+2 only after its h_{t+1}, which needed the consumer's partial_{t+1},
// which needed the consumer's h_t, which required consuming the t value.
// ------------------------------------------------------------------
__global__ void __cluster_dims__(4, 1, 1) __launch_bounds__(320)
rec_kernel(const float *__restrict__ W, const float *__restrict__ A,
           float *__restrict__ Hout) {
    __shared__ __align__(16) float hloc[2][80];              // my h chunk (+pad 0)
    __shared__ __align__(16) unsigned long long inbox[2][4][76]; // [pb][src][slot]

    const int tid  = threadIdx.x;
    const int rank = blockIdx.x & 3;
    const int b    = blockIdx.x >> 2;
    const bool active = tid < 300;
    const int dst  = active ? (tid / 75) : 0;    // owner CTA of row tid
    const int slot = active ? (tid % 75) : 0;

    // W row-slice: thread j holds W[j, 75*rank .. 75*rank+74], packed f32x2.
    unsigned long long w2[38];
    if (active) {
        const float *wp = W + (size_t)tid * HH + rank * 75;
#pragma unroll
        for (int i = 0; i < 37; i++) w2[i] = pack2(wp[2 * i], wp[2 * i + 1]);
        w2[37] = pack2(wp[74], 0.f);
    }
    for (int i = tid; i < 2 * 80; i += blockDim.x) (&hloc[0][0])[i] = 0.f;
    // inbox tags init to 0xFFFFFFFF (never a valid step)
    for (int i = tid; i < 2 * 4 * 76; i += blockDim.x)
        (&inbox[0][0][0])[i] = 0xFFFFFFFF00000000ULL;
    __syncthreads();
    asm volatile("barrier.cluster.arrive.aligned;" ::: "memory");
    asm volatile("barrier.cluster.wait.aligned;" ::: "memory");

    // loop-invariant remote inbox addresses (one per parity)
    unsigned in_rem[2];
    if (active) {
#pragma unroll
        for (int p = 0; p < 2; p++) {
            unsigned lp = smem_u32(&inbox[p][rank][slot]);
            asm("mapa.shared::cluster.u32 %0, %1, %2;"
                : "=r"(in_rem[p]) : "r"(lp), "r"(dst));
        }
    }
    // local poll addresses for finalizers
    unsigned poll[2][4];
    if (tid < 75) {
#pragma unroll
        for (int p = 0; p < 2; p++)
#pragma unroll
            for (int s = 0; s < 4; s++)
                poll[p][s] = smem_u32(&inbox[p][s][tid]);
    }

    const float *arow = A + (size_t)b * HH + rank * 75;
    float *hrow = Hout + (size_t)b * HH + rank * 75;

    float a_cur = (tid < 75) ? arow[tid] : 0.f;

    for (int t = 0; t < SS; t++) {
        const int pb = t & 1;
        float a_nxt = 0.f;
        if (tid < 75 && t + 1 < SS)
            a_nxt = arow[(size_t)(t + 1) * BB * HH + tid];

        if (active) {
            // p_j = dot(W[j, slice], h_slice(t-1));  h(t-1) in hloc[pb^1]
            const ulonglong2 *hp2 =
                reinterpret_cast<const ulonglong2 *>(&hloc[pb ^ 1][0]);
            unsigned long long c0 = 0ULL, c1 = 0ULL, c2 = 0ULL, c3 = 0ULL;
#pragma unroll
            for (int k = 0; k < 19; k++) {
                ulonglong2 hv = hp2[k];
                if (k & 1) { ffma2(c2, w2[2*k], hv.x); ffma2(c3, w2[2*k+1], hv.y); }
                else       { ffma2(c0, w2[2*k], hv.x); ffma2(c1, w2[2*k+1], hv.y); }
            }
            float l0, h0, l1, h1, l2, h2, l3, h3;
            unpack2(c0, l0, h0); unpack2(c1, l1, h1);
            unpack2(c2, l2, h2); unpack2(c3, l3, h3);
            float p = ((l0 + h0) + (l1 + h1)) + ((l2 + h2) + (l3 + h3));
            // tagged message: {value, step}
            unsigned long long msg;
            asm("mov.b64 %0, {%1, %2};"
                : "=l"(msg) : "r"(__float_as_uint(p)), "r"((unsigned)t));
            asm volatile("st.relaxed.cluster.shared::cluster.b64 [%0], %1;"
                         :: "r"(in_rem[pb]), "l"(msg) : "memory");
        }

        if (tid < 75) {
            const unsigned want = (unsigned)t;
            float s = a_cur;
#pragma unroll
            for (int src = 0; src < 4; src++) {
                unsigned long long v;
                do {
                    asm volatile("ld.relaxed.cluster.shared::cta.b64 %0, [%1];"
                                 : "=l"(v) : "r"(poll[pb][src]) : "memory");
                } while ((unsigned)(v >> 32) != want);
                s += __uint_as_float((unsigned)v);
            }
            float hv = tanh_fast(s);
            hrow[(size_t)t * BB * HH + tid] = hv;
            hloc[pb][tid] = hv;
        }
        a_cur = a_nxt;
        __syncthreads();   // publish hloc[pb] for step t+1
    }

    // no peer may still target our SMEM after exit
    asm volatile("barrier.cluster.arrive.aligned;" ::: "memory");
    asm volatile("barrier.cluster.wait.aligned;" ::: "memory");
}

// ------------------------------------------------------------------
// Launch sequence
// ------------------------------------------------------------------
extern "C" void kernel_launch(void *const *d_in, const int *in_sizes, int n_in,
                              void *d_out, int out_size) {
    const int   *x     = (const int *)d_in[0];
    const float *emb   = (const float *)d_in[1];
    const float *W_ih1 = (const float *)d_in[2];
    const float *W_hh1 = (const float *)d_in[3];
    const float *b_ih1 = (const float *)d_in[4];
    const float *b_hh1 = (const float *)d_in[5];
    const float *W_ih2 = (const float *)d_in[6];
    const float *W_hh2 = (const float *)d_in[7];
    const float *b_ih2 = (const float *)d_in[8];
    const float *b_hh2 = (const float *)d_in[9];
    const float *fc1_w = (const float *)d_in[10];
    const float *fc1_b = (const float *)d_in[11];
    const float *fc2_w = (const float *)d_in[12];
    const float *fc2_b = (const float *)d_in[13];
    float *out = (float *)d_out;

    float *xe, *a, *h1, *h2;
    cudaGetSymbolAddress((void **)&xe, g_XE);
    cudaGetSymbolAddress((void **)&a,  g_A);
    cudaGetSymbolAddress((void **)&h1, g_H1);
    cudaGetSymbolAddress((void **)&h2, g_H2);

    // 1) embed + relu
    embed_kernel<<<MROWS, 128>>>(x, emb);

    // 2) A1 = XE @ W_ih1^T + (b_ih1 + b_hh1)
    {
        dim3 grid((HH + 127) / 128, MROWS / 128);
        gemm_nt<false><<<grid, 256>>>(xe, W_ih1, b_ih1, b_hh1, a,
                                      MROWS, HH, K1, HH);
    }
    // 3) layer-1 recurrence -> H1
    rec_kernel<<<128, 320>>>(W_hh1, a, h1);

    // 4) A2 = H1 @ W_ih2^T + (b_ih2 + b_hh2)
    {
        dim3 grid((HH + 127) / 128, MROWS / 128);
        gemm_nt<false><<<grid, 256>>>(h1, W_ih2, b_ih2, b_hh2, a,
                                      MROWS, HH, HH, HH);
    }
    // 5) layer-2 recurrence -> H2
    rec_kernel<<<128, 320>>>(W_hh2, a, h2);

    // 6) projections (permuted store: m = s*32+b -> row b*512+s)
    {
        dim3 grid((NOUT + 127) / 128, MROWS / 128);
        gemm_nt<true><<<grid, 256>>>(h1, fc1_w, fc1_b, nullptr, out,
                                     MROWS, NOUT, HH, NOUT);
        gemm_nt<true><<<grid, 256>>>(h2, fc2_w, fc2_b, nullptr,
                                     out + (size_t)MROWS * NOUT,
                                     MROWS, NOUT, HH, NOUT);
    }
}

// round 9
// speedup vs baseline: 1.4539x; 1.0532x over previous
#include <cuda_runtime.h>
#include <cuda_bf16.h>

// Problem dims
#define BB    32
#define SS    512
#define WIN   5
#define EMB   300
#define HH    300
#define K1    1500        // EMB*WIN
#define NOUT  128
#define MROWS (BB*SS)     // 16384

// ------------------------------------------------------------------
// Scratch (static device globals)
// ------------------------------------------------------------------
__device__ float g_XE[(size_t)MROWS * K1];   // relu(embedded)
__device__ float g_A [(size_t)MROWS * HH];   // A1 pre-activation
__device__ float g_H1[(size_t)MROWS * HH];   // layer1 hidden states [s*32+b][300]
__device__ float g_H2[(size_t)MROWS * HH];   // layer2 hidden states

// ------------------------------------------------------------------
// helpers
// ------------------------------------------------------------------
__device__ __forceinline__ void ffma2(unsigned long long &d,
                                      unsigned long long a,
                                      unsigned long long b) {
    asm("fma.rn.f32x2 %0, %1, %2, %0;" : "+l"(d) : "l"(a), "l"(b));
}
__device__ __forceinline__ unsigned long long pack2(float lo, float hi) {
    unsigned long long r;
    asm("mov.b64 %0, {%1, %2};" : "=l"(r) : "f"(lo), "f"(hi));
    return r;
}
__device__ __forceinline__ void unpack2(unsigned long long v, float &lo, float &hi) {
    asm("mov.b64 {%0, %1}, %2;" : "=f"(lo), "=f"(hi) : "l"(v));
}
__device__ __forceinline__ unsigned smem_u32(const void *p) {
    unsigned a;
    asm("{ .reg .u64 t; cvta.to.shared.u64 t, %1; cvt.u32.u64 %0, t; }"
        : "=r"(a) : "l"(p));
    return a;
}
// tanh via MUFU: 1 - 2/(exp2(2x*log2e)+1). abs err ~1e-7, no division.
__device__ __forceinline__ float tanh_fast(float x) {
    float e;
    asm("ex2.approx.f32 %0, %1;" : "=f"(e) : "f"(x * 2.88539008177792681f));
    float r;
    asm("rcp.approx.f32 %0, %1;" : "=f"(r) : "f"(e + 1.0f));
    return fmaf(-2.0f, r, 1.0f);
}

// ------------------------------------------------------------------
// Kernel 1: embedding gather + relu
// ------------------------------------------------------------------
__global__ void embed_kernel(const int *__restrict__ x,
                             const float *__restrict__ emb) {
    int m = blockIdx.x;            // m = s*32 + b
    int s = m >> 5, b = m & 31;
    __shared__ int idx[WIN];
    if (threadIdx.x < WIN) idx[threadIdx.x] = x[(b * SS + s) * WIN + threadIdx.x];
    __syncthreads();
    float4 *out4 = reinterpret_cast<float4 *>(g_XE + (size_t)m * K1);
    for (int i = threadIdx.x; i < K1 / 4; i += blockDim.x) {
        int e4 = i * 4;
        int w = e4 / EMB;
        int e = e4 - w * EMB;
        float4 v = *reinterpret_cast<const float4 *>(emb + (size_t)idx[w] * EMB + e);
        v.x = fmaxf(v.x, 0.f); v.y = fmaxf(v.y, 0.f);
        v.z = fmaxf(v.z, 0.f); v.w = fmaxf(v.w, 0.f);
        out4[i] = v;
    }
}

// ------------------------------------------------------------------
// GEMM (R8 version, proven): BM=128, BN=128, BK=16, 256 thr, 8x8 tile.
// ------------------------------------------------------------------
template <bool PERM>
__global__ __launch_bounds__(256)
void gemm_nt(const float *__restrict__ A, const float *__restrict__ Bw,
             const float *__restrict__ b1, const float *__restrict__ b2,
             float *__restrict__ C, int M, int N, int K, int ldc) {
    __shared__ __align__(16) float As[2][16][132];
    __shared__ __align__(16) float Bs[2][16][132];

    const int tid = threadIdx.x;
    const int m0 = blockIdx.y * 128;
    const int n0 = blockIdx.x * 128;
    const int tx = tid & 15;
    const int ty = tid >> 4;
    const int lr = tid >> 1;
    const int lk = (tid & 1) * 8;

    unsigned long long acc[8][4];
#pragma unroll
    for (int i = 0; i < 8; i++)
#pragma unroll
        for (int j = 0; j < 4; j++) acc[i][j] = 0ULL;

    const int KT = (K + 15) >> 4;

    {
        float4 a0 = make_float4(0.f,0.f,0.f,0.f), a1 = a0, v0 = a0, v1 = a0;
        int kk = lk;
        const float *ap = A + (size_t)(m0 + lr) * K;
        if (kk     < K) a0 = *reinterpret_cast<const float4 *>(ap + kk);
        if (kk + 4 < K) a1 = *reinterpret_cast<const float4 *>(ap + kk + 4);
        if (n0 + lr < N) {
            const float *bp = Bw + (size_t)(n0 + lr) * K;
            if (kk     < K) v0 = *reinterpret_cast<const float4 *>(bp + kk);
            if (kk + 4 < K) v1 = *reinterpret_cast<const float4 *>(bp + kk + 4);
        }
        As[0][lk+0][lr]=a0.x; As[0][lk+1][lr]=a0.y; As[0][lk+2][lr]=a0.z; As[0][lk+3][lr]=a0.w;
        As[0][lk+4][lr]=a1.x; As[0][lk+5][lr]=a1.y; As[0][lk+6][lr]=a1.z; As[0][lk+7][lr]=a1.w;
        Bs[0][lk+0][lr]=v0.x; Bs[0][lk+1][lr]=v0.y; Bs[0][lk+2][lr]=v0.z; Bs[0][lk+3][lr]=v0.w;
        Bs[0][lk+4][lr]=v1.x; Bs[0][lk+5][lr]=v1.y; Bs[0][lk+6][lr]=v1.z; Bs[0][lk+7][lr]=v1.w;
    }
    __syncthreads();

    for (int kt = 0; kt < KT; kt++) {
        const int cb = kt & 1;
        float4 a0 = make_float4(0.f,0.f,0.f,0.f), a1 = a0, v0 = a0, v1 = a0;
        const bool more = (kt + 1 < KT);
        if (more) {
            int kk = (kt + 1) * 16 + lk;
            const float *ap = A + (size_t)(m0 + lr) * K;
            if (kk     < K) a0 = *reinterpret_cast<const float4 *>(ap + kk);
            if (kk + 4 < K) a1 = *reinterpret_cast<const float4 *>(ap + kk + 4);
            if (n0 + lr < N) {
                const float *bp = Bw + (size_t)(n0 + lr) * K;
                if (kk     < K) v0 = *reinterpret_cast<const float4 *>(bp + kk);
                if (kk + 4 < K) v1 = *reinterpret_cast<const float4 *>(bp + kk + 4);
            }
        }

#pragma unroll
        for (int k = 0; k < 16; k++) {
            float4 aA = *reinterpret_cast<const float4 *>(&As[cb][k][ty * 8]);
            float4 aB = *reinterpret_cast<const float4 *>(&As[cb][k][ty * 8 + 4]);
            ulonglong2 bA = *reinterpret_cast<const ulonglong2 *>(&Bs[cb][k][tx * 8]);
            ulonglong2 bB = *reinterpret_cast<const ulonglong2 *>(&Bs[cb][k][tx * 8 + 4]);
            unsigned long long p0 = pack2(aA.x, aA.x), p1 = pack2(aA.y, aA.y);
            unsigned long long p2 = pack2(aA.z, aA.z), p3 = pack2(aA.w, aA.w);
            unsigned long long p4 = pack2(aB.x, aB.x), p5 = pack2(aB.y, aB.y);
            unsigned long long p6 = pack2(aB.z, aB.z), p7 = pack2(aB.w, aB.w);
            ffma2(acc[0][0], p0, bA.x); ffma2(acc[0][1], p0, bA.y);
            ffma2(acc[0][2], p0, bB.x); ffma2(acc[0][3], p0, bB.y);
            ffma2(acc[1][0], p1, bA.x); ffma2(acc[1][1], p1, bA.y);
            ffma2(acc[1][2], p1, bB.x); ffma2(acc[1][3], p1, bB.y);
            ffma2(acc[2][0], p2, bA.x); ffma2(acc[2][1], p2, bA.y);
            ffma2(acc[2][2], p2, bB.x); ffma2(acc[2][3], p2, bB.y);
            ffma2(acc[3][0], p3, bA.x); ffma2(acc[3][1], p3, bA.y);
            ffma2(acc[3][2], p3, bB.x); ffma2(acc[3][3], p3, bB.y);
            ffma2(acc[4][0], p4, bA.x); ffma2(acc[4][1], p4, bA.y);
            ffma2(acc[4][2], p4, bB.x); ffma2(acc[4][3], p4, bB.y);
            ffma2(acc[5][0], p5, bA.x); ffma2(acc[5][1], p5, bA.y);
            ffma2(acc[5][2], p5, bB.x); ffma2(acc[5][3], p5, bB.y);
            ffma2(acc[6][0], p6, bA.x); ffma2(acc[6][1], p6, bA.y);
            ffma2(acc[6][2], p6, bB.x); ffma2(acc[6][3], p6, bB.y);
            ffma2(acc[7][0], p7, bA.x); ffma2(acc[7][1], p7, bA.y);
            ffma2(acc[7][2], p7, bB.x); ffma2(acc[7][3], p7, bB.y);
        }

        if (more) {
            const int nb = cb ^ 1;
            As[nb][lk+0][lr]=a0.x; As[nb][lk+1][lr]=a0.y; As[nb][lk+2][lr]=a0.z; As[nb][lk+3][lr]=a0.w;
            As[nb][lk+4][lr]=a1.x; As[nb][lk+5][lr]=a1.y; As[nb][lk+6][lr]=a1.z; As[nb][lk+7][lr]=a1.w;
            Bs[nb][lk+0][lr]=v0.x; Bs[nb][lk+1][lr]=v0.y; Bs[nb][lk+2][lr]=v0.z; Bs[nb][lk+3][lr]=v0.w;
            Bs[nb][lk+4][lr]=v1.x; Bs[nb][lk+5][lr]=v1.y; Bs[nb][lk+6][lr]=v1.z; Bs[nb][lk+7][lr]=v1.w;
        }
        __syncthreads();
    }

    float bias[8];
#pragma unroll
    for (int jj = 0; jj < 8; jj++) {
        int n = n0 + tx * 8 + jj;
        bias[jj] = (n < N) ? (b1[n] + (b2 ? b2[n] : 0.f)) : 0.f;
    }
    const int nbase = n0 + tx * 8;
    const bool full = (nbase + 8 <= N);
#pragma unroll
    for (int i = 0; i < 8; i++) {
        int m = m0 + ty * 8 + i;
        int row = PERM ? ((m & 31) * SS + (m >> 5)) : m;
        float *cp = C + (size_t)row * ldc;
        float v[8];
#pragma unroll
        for (int j = 0; j < 4; j++) {
            float lo, hi;
            unpack2(acc[i][j], lo, hi);
            v[2*j]   = lo + bias[2*j];
            v[2*j+1] = hi + bias[2*j+1];
        }
        if (full) {
            *reinterpret_cast<float4 *>(cp + nbase)     = make_float4(v[0], v[1], v[2], v[3]);
            *reinterpret_cast<float4 *>(cp + nbase + 4) = make_float4(v[4], v[5], v[6], v[7]);
        } else {
#pragma unroll
            for (int j = 0; j < 8; j++)
                if (nbase + j < N) cp[nbase + j] = v[j];
        }
    }
}

// ------------------------------------------------------------------
// FUSED two-layer recurrence, software-pipelined (h2 lags h1 by one step).
// One batch element per 4-CTA cluster; CTA r owns k/row chunk r (75 wide).
// Per step t (t = 0..SS inclusive):
//   h1_t     = tanh(A1[t]   + W_hh1 h1_{t-1})                 (if t < SS)
//   h2_{t-1} = tanh(bias2 + W_ih2 h1_{t-1} + W_hh2 h2_{t-2})  (if t >= 1)
// Both dots use only LOCAL h chunks (K-split); partial sums cross CTAs as
// tagged {f32,u32} relaxed b64 messages (R8 mechanism), ONE window per step.
// W_hh1, W_ih2 row-slices live in registers (76+76 regs); W_hh2 chunk lives
// in SMEM (transposed float4 layout, conflict-free lane-consecutive loads).
// Dynamic SMEM layout (bytes):
//   [0, 91200)        Whh2s[q][j] float4, q<19, j<300 (cols 4q..4q+3 of chunk)
//   [91200, 91840)    h1loc[2][80]
//   [91840, 92480)    h2loc[2][80]
//   [92480, 97344)    inbox1[2][4][76] b64
//   [97344, 102208)   inbox2[2][4][76] b64
// ------------------------------------------------------------------
#define OFF_W    0
#define OFF_H1   91200
#define OFF_H2   91840
#define OFF_IB1  92480
#define OFF_IB2  97344
#define REC_SMEM 102208

__global__ void __cluster_dims__(4, 1, 1) __launch_bounds__(320, 1)
rec_fused(const float *__restrict__ Whh1, const float *__restrict__ Wih2,
          const float *__restrict__ Whh2, const float *__restrict__ bih2,
          const float *__restrict__ bhh2, const float *__restrict__ A,
          float *__restrict__ H1out, float *__restrict__ H2out) {
    extern __shared__ __align__(16) char smem[];
    float *h1loc = reinterpret_cast<float *>(smem + OFF_H1);           // [2][80]
    float *h2loc = reinterpret_cast<float *>(smem + OFF_H2);           // [2][80]
    unsigned long long *ib1 = reinterpret_cast<unsigned long long *>(smem + OFF_IB1);
    unsigned long long *ib2 = reinterpret_cast<unsigned long long *>(smem + OFF_IB2);

    const int tid  = threadIdx.x;
    const int rank = blockIdx.x & 3;
    const int b    = blockIdx.x >> 2;
    const bool active = tid < 300;
    const int dst  = active ? (tid / 75) : 0;
    const int slot = active ? (tid % 75) : 0;

    // register-resident W slices: W_hh1[tid, 75r:+75], W_ih2[tid, 75r:+75]
    unsigned long long w1[38], wi[38];
    if (active) {
        const float *p1 = Whh1 + (size_t)tid * HH + rank * 75;
        const float *p2 = Wih2 + (size_t)tid * HH + rank * 75;
#pragma unroll
        for (int i = 0; i < 37; i++) {
            w1[i] = pack2(p1[2 * i], p1[2 * i + 1]);
            wi[i] = pack2(p2[2 * i], p2[2 * i + 1]);
        }
        w1[37] = pack2(p1[74], 0.f);
        wi[37] = pack2(p2[74], 0.f);
    }

    // fill Whh2s: entry e = q*300 + j  ->  float4 of W_hh2[j, 75r+4q .. +3]
    {
        float4 *Ws = reinterpret_cast<float4 *>(smem + OFF_W);
        for (int e = tid; e < 19 * 300; e += 320) {
            int q = e / 300, j = e - q * 300;
            const float *wp = Whh2 + (size_t)j * HH + rank * 75 + 4 * q;
            int c0 = 4 * q;
            float4 v;
            v.x = (c0 + 0 < 75) ? wp[0] : 0.f;
            v.y = (c0 + 1 < 75) ? wp[1] : 0.f;
            v.z = (c0 + 2 < 75) ? wp[2] : 0.f;
            v.w = (c0 + 3 < 75) ? wp[3] : 0.f;
            Ws[e] = v;
        }
    }
    for (int i = tid; i < 2 * 80; i += 320) { h1loc[i] = 0.f; h2loc[i] = 0.f; }
    for (int i = tid; i < 2 * 4 * 76; i += 320) {
        ib1[i] = 0xFFFFFFFF00000000ULL;
        ib2[i] = 0xFFFFFFFF00000000ULL;
    }
    __syncthreads();
    asm volatile("barrier.cluster.arrive.aligned;" ::: "memory");
    asm volatile("barrier.cluster.wait.aligned;" ::: "memory");

    // loop-invariant remote inbox addresses
    unsigned in1_rem[2], in2_rem[2];
    if (active) {
#pragma unroll
        for (int p = 0; p < 2; p++) {
            unsigned l1 = smem_u32(&ib1[(p * 4 + rank) * 76 + slot]);
            unsigned l2 = smem_u32(&ib2[(p * 4 + rank) * 76 + slot]);
            asm("mapa.shared::cluster.u32 %0, %1, %2;" : "=r"(in1_rem[p]) : "r"(l1), "r"(dst));
            asm("mapa.shared::cluster.u32 %0, %1, %2;" : "=r"(in2_rem[p]) : "r"(l2), "r"(dst));
        }
    }
    // finalizer poll addresses
    const bool fin1 = (tid < 75);
    const bool fin2 = (tid >= 96 && tid < 171);
    const int  sl2  = tid - 96;
    unsigned poll1[2][4], poll2[2][4];
    if (fin1) {
#pragma unroll
        for (int p = 0; p < 2; p++)
#pragma unroll
            for (int s = 0; s < 4; s++)
                poll1[p][s] = smem_u32(&ib1[(p * 4 + s) * 76 + tid]);
    }
    float bias2 = 0.f;
    if (fin2) {
#pragma unroll
        for (int p = 0; p < 2; p++)
#pragma unroll
            for (int s = 0; s < 4; s++)
                poll2[p][s] = smem_u32(&ib2[(p * 4 + s) * 76 + sl2]);
        int row = 75 * rank + sl2;
        bias2 = bih2[row] + bhh2[row];
    }

    const float *arow = A + (size_t)b * HH + rank * 75;
    float *h1row = H1out + (size_t)b * HH + rank * 75;
    float *h2row = H2out + (size_t)b * HH + rank * 75;
    const ulonglong2 *Ws2 = reinterpret_cast<const ulonglong2 *>(smem + OFF_W);

    float a_cur = fin1 ? arow[tid] : 0.f;

    for (int t = 0; t <= SS; t++) {
        const int pb = t & 1;
        float a_nxt = 0.f;
        if (fin1 && t + 1 < SS)
            a_nxt = arow[(size_t)(t + 1) * BB * HH + tid];

        if (active) {
            // --- L1 and W_ih2 dots (both on h1_{t-1} = h1loc[pb^1]) ---
            const ulonglong2 *hp1 =
                reinterpret_cast<const ulonglong2 *>(&h1loc[(pb ^ 1) * 80]);
            const ulonglong2 *hp2 =
                reinterpret_cast<const ulonglong2 *>(&h2loc[pb * 80]);   // h2_{t-2}
            unsigned long long c0 = 0, c1 = 0, d0 = 0, d1 = 0, e0 = 0, e1 = 0;
#pragma unroll
            for (int k = 0; k < 19; k++) {
                ulonglong2 hv = hp1[k];
                ffma2(c0, w1[2 * k], hv.x); ffma2(c1, w1[2 * k + 1], hv.y);
                ffma2(d0, wi[2 * k], hv.x); ffma2(d1, wi[2 * k + 1], hv.y);
                ulonglong2 wv = Ws2[(k * 300 + tid)];
                ulonglong2 h2v = hp2[k];
                ffma2(e0, wv.x, h2v.x); ffma2(e1, wv.y, h2v.y);
            }
            float x0, x1, y0, y1;
            unpack2(c0, x0, x1); unpack2(c1, y0, y1);
            float p1v = (x0 + x1) + (y0 + y1);
            unpack2(d0, x0, x1); unpack2(d1, y0, y1);
            float piv = (x0 + x1) + (y0 + y1);
            unpack2(e0, x0, x1); unpack2(e1, y0, y1);
            float p2v = piv + (x0 + x1) + (y0 + y1);

            if (t < SS) {
                unsigned long long msg;
                asm("mov.b64 %0, {%1, %2};"
                    : "=l"(msg) : "r"(__float_as_uint(p1v)), "r"((unsigned)t));
                asm volatile("st.relaxed.cluster.shared::cluster.b64 [%0], %1;"
                             :: "r"(in1_rem[pb]), "l"(msg) : "memory");
            }
            if (t >= 1) {
                unsigned long long msg;
                asm("mov.b64 %0, {%1, %2};"
                    : "=l"(msg) : "r"(__float_as_uint(p2v)), "r"((unsigned)t));
                asm volatile("st.relaxed.cluster.shared::cluster.b64 [%0], %1;"
                             :: "r"(in2_rem[pb]), "l"(msg) : "memory");
            }
        }

        if (fin1 && t < SS) {
            const unsigned want = (unsigned)t;
            float s = a_cur;
#pragma unroll
            for (int src = 0; src < 4; src++) {
                unsigned long long v;
                do {
                    asm volatile("ld.relaxed.cluster.shared::cta.b64 %0, [%1];"
                                 : "=l"(v) : "r"(poll1[pb][src]) : "memory");
                } while ((unsigned)(v >> 32) != want);
                s += __uint_as_float((unsigned)v);
            }
            float hv = tanh_fast(s);
            h1row[(size_t)t * BB * HH + tid] = hv;
            h1loc[pb * 80 + tid] = hv;
        }
        if (fin2 && t >= 1) {
            const unsigned want = (unsigned)t;
            float s = bias2;
#pragma unroll
            for (int src = 0; src < 4; src++) {
                unsigned long long v;
                do {
                    asm volatile("ld.relaxed.cluster.shared::cta.b64 %0, [%1];"
                                 : "=l"(v) : "r"(poll2[pb][src]) : "memory");
                } while ((unsigned)(v >> 32) != want);
                s += __uint_as_float((unsigned)v);
            }
            float hv = tanh_fast(s);
            h2row[(size_t)(t - 1) * BB * HH + sl2] = hv;
            h2loc[(pb ^ 1) * 80 + sl2] = hv;   // read as h2_{(t+1)-2} next step
        }
        a_cur = a_nxt;
        __syncthreads();
    }

    asm volatile("barrier.cluster.arrive.aligned;" ::: "memory");
    asm volatile("barrier.cluster.wait.aligned;" ::: "memory");
}

// ------------------------------------------------------------------
// Launch sequence
// ------------------------------------------------------------------
extern "C" void kernel_launch(void *const *d_in, const int *in_sizes, int n_in,
                              void *d_out, int out_size) {
    const int   *x     = (const int *)d_in[0];
    const float *emb   = (const float *)d_in[1];
    const float *W_ih1 = (const float *)d_in[2];
    const float *W_hh1 = (const float *)d_in[3];
    const float *b_ih1 = (const float *)d_in[4];
    const float *b_hh1 = (const float *)d_in[5];
    const float *W_ih2 = (const float *)d_in[6];
    const float *W_hh2 = (const float *)d_in[7];
    const float *b_ih2 = (const float *)d_in[8];
    const float *b_hh2 = (const float *)d_in[9];
    const float *fc1_w = (const float *)d_in[10];
    const float *fc1_b = (const float *)d_in[11];
    const float *fc2_w = (const float *)d_in[12];
    const float *fc2_b = (const float *)d_in[13];
    float *out = (float *)d_out;

    float *xe, *a, *h1, *h2;
    cudaGetSymbolAddress((void **)&xe, g_XE);
    cudaGetSymbolAddress((void **)&a,  g_A);
    cudaGetSymbolAddress((void **)&h1, g_H1);
    cudaGetSymbolAddress((void **)&h2, g_H2);

    static int smem_set = 0;
    if (!smem_set) {
        cudaFuncSetAttribute(rec_fused,
                             cudaFuncAttributeMaxDynamicSharedMemorySize,
                             REC_SMEM);
        smem_set = 1;
    }

    // 1) embed + relu
    embed_kernel<<<MROWS, 128>>>(x, emb);

    // 2) A1 = XE @ W_ih1^T + (b_ih1 + b_hh1)
    {
        dim3 grid((HH + 127) / 128, MROWS / 128);
        gemm_nt<false><<<grid, 256>>>(xe, W_ih1, b_ih1, b_hh1, a,
                                      MROWS, HH, K1, HH);
    }
    // 3) fused two-layer recurrence -> H1, H2 (A2 GEMM folded in)
    rec_fused<<<128, 320, REC_SMEM>>>(W_hh1, W_ih2, W_hh2, b_ih2, b_hh2,
                                      a, h1, h2);

    // 4) projections (permuted store: m = s*32+b -> row b*512+s)
    {
        dim3 grid((NOUT + 127) / 128, MROWS / 128);
        gemm_nt<true><<<grid, 256>>>(h1, fc1_w, fc1_b, nullptr, out,
                                     MROWS, NOUT, HH, NOUT);
        gemm_nt<true><<<grid, 256>>>(h2, fc2_w, fc2_b, nullptr,
                                     out + (size_t)MROWS * NOUT,
                                     MROWS, NOUT, HH, NOUT);
    }
}

// round 10
// speedup vs baseline: 1.4564x; 1.0017x over previous
#include <cuda_runtime.h>
#include <cuda_bf16.h>

// Problem dims
#define BB    32
#define SS    512
#define WIN   5
#define EMB   300
#define HH    300
#define K1    1500        // EMB*WIN
#define NOUT  128
#define MROWS (BB*SS)     // 16384

// ------------------------------------------------------------------
// Scratch (static device globals)
// ------------------------------------------------------------------
__device__ float g_XE[(size_t)MROWS * K1];   // relu(embedded)
__device__ float g_A [(size_t)MROWS * HH];   // A1 pre-activation
__device__ float g_H1[(size_t)MROWS * HH];   // layer1 hidden states [s*32+b][300]
__device__ float g_H2[(size_t)MROWS * HH];   // layer2 hidden states

// ------------------------------------------------------------------
// helpers
// ------------------------------------------------------------------
__device__ __forceinline__ void ffma2(unsigned long long &d,
                                      unsigned long long a,
                                      unsigned long long b) {
    asm("fma.rn.f32x2 %0, %1, %2, %0;" : "+l"(d) : "l"(a), "l"(b));
}
__device__ __forceinline__ unsigned long long pack2(float lo, float hi) {
    unsigned long long r;
    asm("mov.b64 %0, {%1, %2};" : "=l"(r) : "f"(lo), "f"(hi));
    return r;
}
__device__ __forceinline__ void unpack2(unsigned long long v, float &lo, float &hi) {
    asm("mov.b64 {%0, %1}, %2;" : "=f"(lo), "=f"(hi) : "l"(v));
}
__device__ __forceinline__ unsigned smem_u32(const void *p) {
    unsigned a;
    asm("{ .reg .u64 t; cvta.to.shared.u64 t, %1; cvt.u32.u64 %0, t; }"
        : "=r"(a) : "l"(p));
    return a;
}
// tanh via MUFU: 1 - 2/(exp2(2x*log2e)+1). abs err ~1e-7, no division.
__device__ __forceinline__ float tanh_fast(float x) {
    float e;
    asm("ex2.approx.f32 %0, %1;" : "=f"(e) : "f"(x * 2.88539008177792681f));
    float r;
    asm("rcp.approx.f32 %0, %1;" : "=f"(r) : "f"(e + 1.0f));
    return fmaf(-2.0f, r, 1.0f);
}

// ------------------------------------------------------------------
// Kernel 1: embedding gather + relu
// ------------------------------------------------------------------
__global__ void embed_kernel(const int *__restrict__ x,
                             const float *__restrict__ emb) {
    int m = blockIdx.x;            // m = s*32 + b
    int s = m >> 5, b = m & 31;
    __shared__ int idx[WIN];
    if (threadIdx.x < WIN) idx[threadIdx.x] = x[(b * SS + s) * WIN + threadIdx.x];
    __syncthreads();
    float4 *out4 = reinterpret_cast<float4 *>(g_XE + (size_t)m * K1);
    for (int i = threadIdx.x; i < K1 / 4; i += blockDim.x) {
        int e4 = i * 4;
        int w = e4 / EMB;
        int e = e4 - w * EMB;
        float4 v = *reinterpret_cast<const float4 *>(emb + (size_t)idx[w] * EMB + e);
        v.x = fmaxf(v.x, 0.f); v.y = fmaxf(v.y, 0.f);
        v.z = fmaxf(v.z, 0.f); v.w = fmaxf(v.w, 0.f);
        out4[i] = v;
    }
}

// ------------------------------------------------------------------
// GEMM (R8 version, proven): BM=128, BN=128, BK=16, 256 thr, 8x8 tile.
// ------------------------------------------------------------------
template <bool PERM>
__global__ __launch_bounds__(256)
void gemm_nt(const float *__restrict__ A, const float *__restrict__ Bw,
             const float *__restrict__ b1, const float *__restrict__ b2,
             float *__restrict__ C, int M, int N, int K, int ldc) {
    __shared__ __align__(16) float As[2][16][132];
    __shared__ __align__(16) float Bs[2][16][132];

    const int tid = threadIdx.x;
    const int m0 = blockIdx.y * 128;
    const int n0 = blockIdx.x * 128;
    const int tx = tid & 15;
    const int ty = tid >> 4;
    const int lr = tid >> 1;
    const int lk = (tid & 1) * 8;

    unsigned long long acc[8][4];
#pragma unroll
    for (int i = 0; i < 8; i++)
#pragma unroll
        for (int j = 0; j < 4; j++) acc[i][j] = 0ULL;

    const int KT = (K + 15) >> 4;

    {
        float4 a0 = make_float4(0.f,0.f,0.f,0.f), a1 = a0, v0 = a0, v1 = a0;
        int kk = lk;
        const float *ap = A + (size_t)(m0 + lr) * K;
        if (kk     < K) a0 = *reinterpret_cast<const float4 *>(ap + kk);
        if (kk + 4 < K) a1 = *reinterpret_cast<const float4 *>(ap + kk + 4);
        if (n0 + lr < N) {
            const float *bp = Bw + (size_t)(n0 + lr) * K;
            if (kk     < K) v0 = *reinterpret_cast<const float4 *>(bp + kk);
            if (kk + 4 < K) v1 = *reinterpret_cast<const float4 *>(bp + kk + 4);
        }
        As[0][lk+0][lr]=a0.x; As[0][lk+1][lr]=a0.y; As[0][lk+2][lr]=a0.z; As[0][lk+3][lr]=a0.w;
        As[0][lk+4][lr]=a1.x; As[0][lk+5][lr]=a1.y; As[0][lk+6][lr]=a1.z; As[0][lk+7][lr]=a1.w;
        Bs[0][lk+0][lr]=v0.x; Bs[0][lk+1][lr]=v0.y; Bs[0][lk+2][lr]=v0.z; Bs[0][lk+3][lr]=v0.w;
        Bs[0][lk+4][lr]=v1.x; Bs[0][lk+5][lr]=v1.y; Bs[0][lk+6][lr]=v1.z; Bs[0][lk+7][lr]=v1.w;
    }
    __syncthreads();

    for (int kt = 0; kt < KT; kt++) {
        const int cb = kt & 1;
        float4 a0 = make_float4(0.f,0.f,0.f,0.f), a1 = a0, v0 = a0, v1 = a0;
        const bool more = (kt + 1 < KT);
        if (more) {
            int kk = (kt + 1) * 16 + lk;
            const float *ap = A + (size_t)(m0 + lr) * K;
            if (kk     < K) a0 = *reinterpret_cast<const float4 *>(ap + kk);
            if (kk + 4 < K) a1 = *reinterpret_cast<const float4 *>(ap + kk + 4);
            if (n0 + lr < N) {
                const float *bp = Bw + (size_t)(n0 + lr) * K;
                if (kk     < K) v0 = *reinterpret_cast<const float4 *>(bp + kk);
                if (kk + 4 < K) v1 = *reinterpret_cast<const float4 *>(bp + kk + 4);
            }
        }

#pragma unroll
        for (int k = 0; k < 16; k++) {
            float4 aA = *reinterpret_cast<const float4 *>(&As[cb][k][ty * 8]);
            float4 aB = *reinterpret_cast<const float4 *>(&As[cb][k][ty * 8 + 4]);
            ulonglong2 bA = *reinterpret_cast<const ulonglong2 *>(&Bs[cb][k][tx * 8]);
            ulonglong2 bB = *reinterpret_cast<const ulonglong2 *>(&Bs[cb][k][tx * 8 + 4]);
            unsigned long long p0 = pack2(aA.x, aA.x), p1 = pack2(aA.y, aA.y);
            unsigned long long p2 = pack2(aA.z, aA.z), p3 = pack2(aA.w, aA.w);
            unsigned long long p4 = pack2(aB.x, aB.x), p5 = pack2(aB.y, aB.y);
            unsigned long long p6 = pack2(aB.z, aB.z), p7 = pack2(aB.w, aB.w);
            ffma2(acc[0][0], p0, bA.x); ffma2(acc[0][1], p0, bA.y);
            ffma2(acc[0][2], p0, bB.x); ffma2(acc[0][3], p0, bB.y);
            ffma2(acc[1][0], p1, bA.x); ffma2(acc[1][1], p1, bA.y);
            ffma2(acc[1][2], p1, bB.x); ffma2(acc[1][3], p1, bB.y);
            ffma2(acc[2][0], p2, bA.x); ffma2(acc[2][1], p2, bA.y);
            ffma2(acc[2][2], p2, bB.x); ffma2(acc[2][3], p2, bB.y);
            ffma2(acc[3][0], p3, bA.x); ffma2(acc[3][1], p3, bA.y);
            ffma2(acc[3][2], p3, bB.x); ffma2(acc[3][3], p3, bB.y);
            ffma2(acc[4][0], p4, bA.x); ffma2(acc[4][1], p4, bA.y);
            ffma2(acc[4][2], p4, bB.x); ffma2(acc[4][3], p4, bB.y);
            ffma2(acc[5][0], p5, bA.x); ffma2(acc[5][1], p5, bA.y);
            ffma2(acc[5][2], p5, bB.x); ffma2(acc[5][3], p5, bB.y);
            ffma2(acc[6][0], p6, bA.x); ffma2(acc[6][1], p6, bA.y);
            ffma2(acc[6][2], p6, bB.x); ffma2(acc[6][3], p6, bB.y);
            ffma2(acc[7][0], p7, bA.x); ffma2(acc[7][1], p7, bA.y);
            ffma2(acc[7][2], p7, bB.x); ffma2(acc[7][3], p7, bB.y);
        }

        if (more) {
            const int nb = cb ^ 1;
            As[nb][lk+0][lr]=a0.x; As[nb][lk+1][lr]=a0.y; As[nb][lk+2][lr]=a0.z; As[nb][lk+3][lr]=a0.w;
            As[nb][lk+4][lr]=a1.x; As[nb][lk+5][lr]=a1.y; As[nb][lk+6][lr]=a1.z; As[nb][lk+7][lr]=a1.w;
            Bs[nb][lk+0][lr]=v0.x; Bs[nb][lk+1][lr]=v0.y; Bs[nb][lk+2][lr]=v0.z; Bs[nb][lk+3][lr]=v0.w;
            Bs[nb][lk+4][lr]=v1.x; Bs[nb][lk+5][lr]=v1.y; Bs[nb][lk+6][lr]=v1.z; Bs[nb][lk+7][lr]=v1.w;
        }
        __syncthreads();
    }

    float bias[8];
#pragma unroll
    for (int jj = 0; jj < 8; jj++) {
        int n = n0 + tx * 8 + jj;
        bias[jj] = (n < N) ? (b1[n] + (b2 ? b2[n] : 0.f)) : 0.f;
    }
    const int nbase = n0 + tx * 8;
    const bool full = (nbase + 8 <= N);
#pragma unroll
    for (int i = 0; i < 8; i++) {
        int m = m0 + ty * 8 + i;
        int row = PERM ? ((m & 31) * SS + (m >> 5)) : m;
        float *cp = C + (size_t)row * ldc;
        float v[8];
#pragma unroll
        for (int j = 0; j < 4; j++) {
            float lo, hi;
            unpack2(acc[i][j], lo, hi);
            v[2*j]   = lo + bias[2*j];
            v[2*j+1] = hi + bias[2*j+1];
        }
        if (full) {
            *reinterpret_cast<float4 *>(cp + nbase)     = make_float4(v[0], v[1], v[2], v[3]);
            *reinterpret_cast<float4 *>(cp + nbase + 4) = make_float4(v[4], v[5], v[6], v[7]);
        } else {
#pragma unroll
            for (int j = 0; j < 8; j++)
                if (nbase + j < N) cp[nbase + j] = v[j];
        }
    }
}

// ------------------------------------------------------------------
// FUSED two-layer recurrence, software-pipelined (h2 lags h1 by one step).
// One batch element per 4-CTA cluster; CTA r owns k/row chunk r (75 wide).
// Per step t (t = 0..SS inclusive):
//   h1_t     = tanh(A1[t]   + W_hh1 h1_{t-1})                 (if t < SS)
//   h2_{t-1} = tanh(bias2 + W_ih2 h1_{t-1} + W_hh2 h2_{t-2})  (if t >= 1)
// Both dots use only LOCAL h chunks (K-split); partial sums cross CTAs as
// tagged {f32,u32} relaxed b64 messages (R8 mechanism), ONE window per step.
// W_hh1, W_ih2 row-slices live in registers (76+76 regs); W_hh2 chunk lives
// in SMEM (transposed float4 layout, conflict-free lane-consecutive loads).
// Dynamic SMEM layout (bytes):
//   [0, 91200)        Whh2s[q][j] float4, q<19, j<300 (cols 4q..4q+3 of chunk)
//   [91200, 91840)    h1loc[2][80]
//   [91840, 92480)    h2loc[2][80]
//   [92480, 97344)    inbox1[2][4][76] b64
//   [97344, 102208)   inbox2[2][4][76] b64
// ------------------------------------------------------------------
#define OFF_W    0
#define OFF_H1   91200
#define OFF_H2   91840
#define OFF_IB1  92480
#define OFF_IB2  97344
#define REC_SMEM 102208

__global__ void __cluster_dims__(4, 1, 1) __launch_bounds__(320, 1)
rec_fused(const float *__restrict__ Whh1, const float *__restrict__ Wih2,
          const float *__restrict__ Whh2, const float *__restrict__ bih2,
          const float *__restrict__ bhh2, const float *__restrict__ A,
          float *__restrict__ H1out, float *__restrict__ H2out) {
    extern __shared__ __align__(16) char smem[];
    float *h1loc = reinterpret_cast<float *>(smem + OFF_H1);           // [2][80]
    float *h2loc = reinterpret_cast<float *>(smem + OFF_H2);           // [2][80]
    unsigned long long *ib1 = reinterpret_cast<unsigned long long *>(smem + OFF_IB1);
    unsigned long long *ib2 = reinterpret_cast<unsigned long long *>(smem + OFF_IB2);

    const int tid  = threadIdx.x;
    const int rank = blockIdx.x & 3;
    const int b    = blockIdx.x >> 2;
    const bool active = tid < 300;
    const int dst  = active ? (tid / 75) : 0;
    const int slot = active ? (tid % 75) : 0;

    // register-resident W slices: W_hh1[tid, 75r:+75], W_ih2[tid, 75r:+75]
    unsigned long long w1[38], wi[38];
    if (active) {
        const float *p1 = Whh1 + (size_t)tid * HH + rank * 75;
        const float *p2 = Wih2 + (size_t)tid * HH + rank * 75;
#pragma unroll
        for (int i = 0; i < 37; i++) {
            w1[i] = pack2(p1[2 * i], p1[2 * i + 1]);
            wi[i] = pack2(p2[2 * i], p2[2 * i + 1]);
        }
        w1[37] = pack2(p1[74], 0.f);
        wi[37] = pack2(p2[74], 0.f);
    }

    // fill Whh2s: entry e = q*300 + j  ->  float4 of W_hh2[j, 75r+4q .. +3]
    {
        float4 *Ws = reinterpret_cast<float4 *>(smem + OFF_W);
        for (int e = tid; e < 19 * 300; e += 320) {
            int q = e / 300, j = e - q * 300;
            const float *wp = Whh2 + (size_t)j * HH + rank * 75 + 4 * q;
            int c0 = 4 * q;
            float4 v;
            v.x = (c0 + 0 < 75) ? wp[0] : 0.f;
            v.y = (c0 + 1 < 75) ? wp[1] : 0.f;
            v.z = (c0 + 2 < 75) ? wp[2] : 0.f;
            v.w = (c0 + 3 < 75) ? wp[3] : 0.f;
            Ws[e] = v;
        }
    }
    for (int i = tid; i < 2 * 80; i += 320) { h1loc[i] = 0.f; h2loc[i] = 0.f; }
    for (int i = tid; i < 2 * 4 * 76; i += 320) {
        ib1[i] = 0xFFFFFFFF00000000ULL;
        ib2[i] = 0xFFFFFFFF00000000ULL;
    }
    __syncthreads();
    asm volatile("barrier.cluster.arrive.aligned;" ::: "memory");
    asm volatile("barrier.cluster.wait.aligned;" ::: "memory");

    // loop-invariant remote inbox addresses
    unsigned in1_rem[2], in2_rem[2];
    if (active) {
#pragma unroll
        for (int p = 0; p < 2; p++) {
            unsigned l1 = smem_u32(&ib1[(p * 4 + rank) * 76 + slot]);
            unsigned l2 = smem_u32(&ib2[(p * 4 + rank) * 76 + slot]);
            asm("mapa.shared::cluster.u32 %0, %1, %2;" : "=r"(in1_rem[p]) : "r"(l1), "r"(dst));
            asm("mapa.shared::cluster.u32 %0, %1, %2;" : "=r"(in2_rem[p]) : "r"(l2), "r"(dst));
        }
    }
    // finalizer poll addresses
    const bool fin1 = (tid < 75);
    const bool fin2 = (tid >= 96 && tid < 171);
    const int  sl2  = tid - 96;
    unsigned poll1[2][4], poll2[2][4];
    if (fin1) {
#pragma unroll
        for (int p = 0; p < 2; p++)
#pragma unroll
            for (int s = 0; s < 4; s++)
                poll1[p][s] = smem_u32(&ib1[(p * 4 + s) * 76 + tid]);
    }
    float bias2 = 0.f;
    if (fin2) {
#pragma unroll
        for (int p = 0; p < 2; p++)
#pragma unroll
            for (int s = 0; s < 4; s++)
                poll2[p][s] = smem_u32(&ib2[(p * 4 + s) * 76 + sl2]);
        int row = 75 * rank + sl2;
        bias2 = bih2[row] + bhh2[row];
    }

    const float *arow = A + (size_t)b * HH + rank * 75;
    float *h1row = H1out + (size_t)b * HH + rank * 75;
    float *h2row = H2out + (size_t)b * HH + rank * 75;
    const ulonglong2 *Ws2 = reinterpret_cast<const ulonglong2 *>(smem + OFF_W);

    float a_cur = fin1 ? arow[tid] : 0.f;

    for (int t = 0; t <= SS; t++) {
        const int pb = t & 1;
        float a_nxt = 0.f;
        if (fin1 && t + 1 < SS)
            a_nxt = arow[(size_t)(t + 1) * BB * HH + tid];

        if (active) {
            // --- L1 and W_ih2 dots (both on h1_{t-1} = h1loc[pb^1]) ---
            const ulonglong2 *hp1 =
                reinterpret_cast<const ulonglong2 *>(&h1loc[(pb ^ 1) * 80]);
            const ulonglong2 *hp2 =
                reinterpret_cast<const ulonglong2 *>(&h2loc[pb * 80]);   // h2_{t-2}
            unsigned long long c0 = 0, c1 = 0, d0 = 0, d1 = 0, e0 = 0, e1 = 0;
#pragma unroll
            for (int k = 0; k < 19; k++) {
                ulonglong2 hv = hp1[k];
                ffma2(c0, w1[2 * k], hv.x); ffma2(c1, w1[2 * k + 1], hv.y);
                ffma2(d0, wi[2 * k], hv.x); ffma2(d1, wi[2 * k + 1], hv.y);
                ulonglong2 wv = Ws2[(k * 300 + tid)];
                ulonglong2 h2v = hp2[k];
                ffma2(e0, wv.x, h2v.x); ffma2(e1, wv.y, h2v.y);
            }
            float x0, x1, y0, y1;
            unpack2(c0, x0, x1); unpack2(c1, y0, y1);
            float p1v = (x0 + x1) + (y0 + y1);
            unpack2(d0, x0, x1); unpack2(d1, y0, y1);
            float piv = (x0 + x1) + (y0 + y1);
            unpack2(e0, x0, x1); unpack2(e1, y0, y1);
            float p2v = piv + (x0 + x1) + (y0 + y1);

            if (t < SS) {
                unsigned long long msg;
                asm("mov.b64 %0, {%1, %2};"
                    : "=l"(msg) : "r"(__float_as_uint(p1v)), "r"((unsigned)t));
                asm volatile("st.relaxed.cluster.shared::cluster.b64 [%0], %1;"
                             :: "r"(in1_rem[pb]), "l"(msg) : "memory");
            }
            if (t >= 1) {
                unsigned long long msg;
                asm("mov.b64 %0, {%1, %2};"
                    : "=l"(msg) : "r"(__float_as_uint(p2v)), "r"((unsigned)t));
                asm volatile("st.relaxed.cluster.shared::cluster.b64 [%0], %1;"
                             :: "r"(in2_rem[pb]), "l"(msg) : "memory");
            }
        }

        if (fin1 && t < SS) {
            const unsigned want = (unsigned)t;
            float s = a_cur;
#pragma unroll
            for (int src = 0; src < 4; src++) {
                unsigned long long v;
                do {
                    asm volatile("ld.relaxed.cluster.shared::cta.b64 %0, [%1];"
                                 : "=l"(v) : "r"(poll1[pb][src]) : "memory");
                } while ((unsigned)(v >> 32) != want);
                s += __uint_as_float((unsigned)v);
            }
            float hv = tanh_fast(s);
            h1row[(size_t)t * BB * HH + tid] = hv;
            h1loc[pb * 80 + tid] = hv;
        }
        if (fin2 && t >= 1) {
            const unsigned want = (unsigned)t;
            float s = bias2;
#pragma unroll
            for (int src = 0; src < 4; src++) {
                unsigned long long v;
                do {
                    asm volatile("ld.relaxed.cluster.shared::cta.b64 %0, [%1];"
                                 : "=l"(v) : "r"(poll2[pb][src]) : "memory");
                } while ((unsigned)(v >> 32) != want);
                s += __uint_as_float((unsigned)v);
            }
            float hv = tanh_fast(s);
            h2row[(size_t)(t - 1) * BB * HH + sl2] = hv;
            h2loc[(pb ^ 1) * 80 + sl2] = hv;   // read as h2_{(t+1)-2} next step
        }
        a_cur = a_nxt;
        __syncthreads();
    }

    asm volatile("barrier.cluster.arrive.aligned;" ::: "memory");
    asm volatile("barrier.cluster.wait.aligned;" ::: "memory");
}

// ------------------------------------------------------------------
// Launch sequence
// ------------------------------------------------------------------
extern "C" void kernel_launch(void *const *d_in, const int *in_sizes, int n_in,
                              void *d_out, int out_size) {
    const int   *x     = (const int *)d_in[0];
    const float *emb   = (const float *)d_in[1];
    const float *W_ih1 = (const float *)d_in[2];
    const float *W_hh1 = (const float *)d_in[3];
    const float *b_ih1 = (const float *)d_in[4];
    const float *b_hh1 = (const float *)d_in[5];
    const float *W_ih2 = (const float *)d_in[6];
    const float *W_hh2 = (const float *)d_in[7];
    const float *b_ih2 = (const float *)d_in[8];
    const float *b_hh2 = (const float *)d_in[9];
    const float *fc1_w = (const float *)d_in[10];
    const float *fc1_b = (const float *)d_in[11];
    const float *fc2_w = (const float *)d_in[12];
    const float *fc2_b = (const float *)d_in[13];
    float *out = (float *)d_out;

    float *xe, *a, *h1, *h2;
    cudaGetSymbolAddress((void **)&xe, g_XE);
    cudaGetSymbolAddress((void **)&a,  g_A);
    cudaGetSymbolAddress((void **)&h1, g_H1);
    cudaGetSymbolAddress((void **)&h2, g_H2);

    static int smem_set = 0;
    if (!smem_set) {
        cudaFuncSetAttribute(rec_fused,
                             cudaFuncAttributeMaxDynamicSharedMemorySize,
                             REC_SMEM);
        smem_set = 1;
    }

    // 1) embed + relu
    embed_kernel<<<MROWS, 128>>>(x, emb);

    // 2) A1 = XE @ W_ih1^T + (b_ih1 + b_hh1)
    {
        dim3 grid((HH + 127) / 128, MROWS / 128);
        gemm_nt<false><<<grid, 256>>>(xe, W_ih1, b_ih1, b_hh1, a,
                                      MROWS, HH, K1, HH);
    }
    // 3) fused two-layer recurrence -> H1, H2 (A2 GEMM folded in)
    rec_fused<<<128, 320, REC_SMEM>>>(W_hh1, W_ih2, W_hh2, b_ih2, b_hh2,
                                      a, h1, h2);

    // 4) projections (permuted store: m = s*32+b -> row b*512+s)
    {
        dim3 grid((NOUT + 127) / 128, MROWS / 128);
        gemm_nt<true><<<grid, 256>>>(h1, fc1_w, fc1_b, nullptr, out,
                                     MROWS, NOUT, HH, NOUT);
        gemm_nt<true><<<grid, 256>>>(h2, fc2_w, fc2_b, nullptr,
                                     out + (size_t)MROWS * NOUT,
                                     MROWS, NOUT, HH, NOUT);
    }
}